// round 12
// baseline (speedup 1.0000x reference)
#include <cuda_runtime.h>

#define E_DIM 256
#define H1 32
#define H2 16
#define SIG_ROWS 32          // rows per sigma block
#define SIG_THREADS 256      // 8 threads (g=0..7) per row
#define EPAD 260             // padded e row stride in words (bank spread)
#define ROWS_PER_BLK 8       // stream kernel rows per block
#define MAX_ROWS 32768

// Per-row precomputed exponent constants (base-2, log2e folded in):
//   exponent(m) = a*r2[m] + k0*z0[m] + k1*z1[m] + c,  r2 = z0^2+z1^2
__device__ float4 g_params[MAX_ROWS];

__device__ __forceinline__ float ex2f(float x) {
    float y;
    asm("ex2.approx.f32 %0, %1;" : "=f"(y) : "f"(x));
    return y;
}
__device__ __forceinline__ float gelu_exact(float x) {
    return 0.5f * x * (1.0f + erff(x * 0.70710678118654752f));
}

// ---------------- Kernel 1: sigma MLP ----------------
// 256 threads, 32 rows per block. tid = row*8 + g.
// Lane-group g computes h-columns 4g..4g+3 over all k (no k-split reduction).
extern __shared__ float smem_dyn[];

__global__ __launch_bounds__(SIG_THREADS)
void sigma_kernel(const float* __restrict__ emb,   // [BN, E]
                  const float* __restrict__ mu,    // [BN, 2]
                  const float* __restrict__ w1,    // [E, H1]
                  const float* __restrict__ b1,
                  const float* __restrict__ w2,    // [H1, H2]
                  const float* __restrict__ b2,
                  const float* __restrict__ w3,    // [H2, 1]
                  const float* __restrict__ b3,
                  int BN)
{
    float* w1_sh = smem_dyn;                  // 256*32 floats = 32 KB
    float* e_sh  = smem_dyn + E_DIM * H1;     // 32 rows * EPAD words

    const int tid = threadIdx.x;
    const int rowBase = blockIdx.x * SIG_ROWS;

    // Stage w1 (coalesced): 2048 float4 / 256 threads = 8 iters
    {
        const float4* s = (const float4*)w1;
        float4* d = (float4*)w1_sh;
        #pragma unroll
        for (int i = 0; i < (E_DIM * H1 / 4) / SIG_THREADS; ++i)
            d[tid + i * SIG_THREADS] = s[tid + i * SIG_THREADS];
    }
    // Stage e tile: 32 rows * 64 float4 (coalesced src, padded dst)
    {
        const float4* s = (const float4*)emb + (size_t)rowBase * (E_DIM / 4);
        const size_t base = (size_t)rowBase * (E_DIM / 4);
        const size_t lim  = (size_t)BN * (E_DIM / 4);
        #pragma unroll
        for (int i = 0; i < (SIG_ROWS * E_DIM / 4) / SIG_THREADS; ++i) {
            int idx = tid + i * SIG_THREADS;   // 0..2047
            int rr  = idx >> 6;                // local row
            int cc  = idx & 63;                // float4 col
            float4 v = (base + idx < lim) ? s[idx] : make_float4(0, 0, 0, 0);
            *(float4*)&e_sh[rr * EPAD + cc * 4] = v;
        }
    }
    __syncthreads();

    const int lrow = tid >> 3;    // 0..31
    const int g    = tid & 7;     // 0..7
    const float* erow = e_sh + lrow * EPAD;

    // ---- Layer 1: 4 h-columns per thread, packed f32x2 ----
    unsigned long long a01 = 0ULL, a23 = 0ULL;
    #pragma unroll 8
    for (int k = 0; k < E_DIM; ++k) {
        const float ek = erow[k];                       // broadcast LDS.32
        unsigned long long ekk;
        asm("mov.b64 %0, {%1, %1};" : "=l"(ekk) : "f"(ek));
        const ulonglong2 w = *(const ulonglong2*)(w1_sh + k * H1 + g * 4); // LDS.128
        asm("fma.rn.f32x2 %0, %1, %2, %0;" : "+l"(a01) : "l"(ekk), "l"(w.x));
        asm("fma.rn.f32x2 %0, %1, %2, %0;" : "+l"(a23) : "l"(ekk), "l"(w.y));
    }

    // Unpack + bias + GELU -> 4 h1 values (i = 4g..4g+3)
    float h1v[4];
    {
        float lo, hi;
        const float4 bb = __ldg((const float4*)&b1[g * 4]);
        asm("mov.b64 {%0, %1}, %2;" : "=f"(lo), "=f"(hi) : "l"(a01));
        h1v[0] = gelu_exact(lo + bb.x);
        h1v[1] = gelu_exact(hi + bb.y);
        asm("mov.b64 {%0, %1}, %2;" : "=f"(lo), "=f"(hi) : "l"(a23));
        h1v[2] = gelu_exact(lo + bb.z);
        h1v[3] = gelu_exact(hi + bb.w);
    }

    // ---- Layer 2: partials over my 4 i's for all 16 j ----
    float acc2[16];
    #pragma unroll
    for (int j = 0; j < 16; ++j) acc2[j] = 0.0f;
    #pragma unroll
    for (int ii = 0; ii < 4; ++ii) {
        const int i = g * 4 + ii;
        const float hv = h1v[ii];
        const float4* w2r = (const float4*)(w2 + i * H2);
        #pragma unroll
        for (int jq = 0; jq < 4; ++jq) {
            const float4 w = __ldg(&w2r[jq]);
            acc2[jq * 4 + 0] = fmaf(hv, w.x, acc2[jq * 4 + 0]);
            acc2[jq * 4 + 1] = fmaf(hv, w.y, acc2[jq * 4 + 1]);
            acc2[jq * 4 + 2] = fmaf(hv, w.z, acc2[jq * 4 + 2]);
            acc2[jq * 4 + 3] = fmaf(hv, w.w, acc2[jq * 4 + 3]);
        }
    }
    // Butterfly-sum partials across the 8 g-threads of this row
    #pragma unroll
    for (int j = 0; j < 16; ++j) {
        acc2[j] += __shfl_xor_sync(0xffffffffu, acc2[j], 1);
        acc2[j] += __shfl_xor_sync(0xffffffffu, acc2[j], 2);
        acc2[j] += __shfl_xor_sync(0xffffffffu, acc2[j], 4);
    }

    // ---- Layer 3: thread g handles j = 2g, 2g+1 ----
    float part;
    {
        const int j0 = g * 2;
        const float h2a = gelu_exact(acc2[j0 + 0] + __ldg(&b2[j0 + 0]));
        const float h2b = gelu_exact(acc2[j0 + 1] + __ldg(&b2[j0 + 1]));
        part = fmaf(h2a, __ldg(&w3[j0]), h2b * __ldg(&w3[j0 + 1]));
    }
    part += __shfl_xor_sync(0xffffffffu, part, 1);
    part += __shfl_xor_sync(0xffffffffu, part, 2);
    part += __shfl_xor_sync(0xffffffffu, part, 4);

    const int row = rowBase + lrow;
    if (g == 0 && row < BN) {
        const float s     = part + __ldg(&b3[0]);
        const float sig   = 1.0f / (1.0f + expf(-s));   // accurate, once/row
        const float sigma = 0.1f + 9.9f * sig;
        const float LOG2E = 1.4426950408889634f;
        const float a  = -0.5f * LOG2E / (sigma * sigma);
        const float m0 = mu[row * 2 + 0];
        const float m1 = mu[row * 2 + 1];
        g_params[row] = make_float4(a, -2.0f * a * m0, -2.0f * a * m1,
                                    a * fmaf(m0, m0, m1 * m1));
    }
}

// ---------------- Kernel 2: streaming RBF (R6 config: 8 rows, 512 thr) ----
__global__ __launch_bounds__(512)
void rbf_stream_kernel(const float* __restrict__ z,   // [M, 2]
                       float* __restrict__ out,       // [BN, M]
                       int M, int BN)
{
    __shared__ float4 p_sh[ROWS_PER_BLK];

    const int rowBase = blockIdx.x * ROWS_PER_BLK;
    const int nRows   = min(ROWS_PER_BLK, BN - rowBase);
    const int nQuads  = M >> 2;

    if (threadIdx.x < (unsigned)nRows)
        p_sh[threadIdx.x] = g_params[rowBase + threadIdx.x];
    __syncthreads();

    const float4* __restrict__ z4 = (const float4*)z;

    for (int q = threadIdx.x; q < nQuads; q += blockDim.x) {
        float4 za = z4[2 * q];        // (z0,z1) of m=4q, 4q+1
        float4 zb = z4[2 * q + 1];    // (z0,z1) of m=4q+2, 4q+3

        float r0 = fmaf(za.x, za.x, za.y * za.y);
        float r1 = fmaf(za.z, za.z, za.w * za.w);
        float r2 = fmaf(zb.x, zb.x, zb.y * zb.y);
        float r3 = fmaf(zb.z, zb.z, zb.w * zb.w);

        float4* out4 = (float4*)out + (size_t)rowBase * nQuads + q;

        #pragma unroll
        for (int r = 0; r < ROWS_PER_BLK; ++r) {
            if (r >= nRows) break;
            float4 p = p_sh[r];
            float4 o;
            o.x = ex2f(fmaf(p.x, r0, fmaf(p.y, za.x, fmaf(p.z, za.y, p.w))));
            o.y = ex2f(fmaf(p.x, r1, fmaf(p.y, za.z, fmaf(p.z, za.w, p.w))));
            o.z = ex2f(fmaf(p.x, r2, fmaf(p.y, zb.x, fmaf(p.z, zb.y, p.w))));
            o.w = ex2f(fmaf(p.x, r3, fmaf(p.y, zb.z, fmaf(p.z, zb.w, p.w))));
            out4[(size_t)r * nQuads] = o;
        }
    }
}

extern "C" void kernel_launch(void* const* d_in, const int* in_sizes, int n_in,
                              void* d_out, int out_size)
{
    // metadata order: z, mu, embeddings, w1, b1, w2, b2, w3, b3
    const float* z   = (const float*)d_in[0];
    const float* mu  = (const float*)d_in[1];
    const float* emb = (const float*)d_in[2];
    const float* w1  = (const float*)d_in[3];
    const float* b1  = (const float*)d_in[4];
    const float* w2  = (const float*)d_in[5];
    const float* b2  = (const float*)d_in[6];
    const float* w3  = (const float*)d_in[7];
    const float* b3  = (const float*)d_in[8];
    float* out = (float*)d_out;

    const int M  = in_sizes[0] / 2;      // z is [M, 2]
    const int BN = in_sizes[2] / E_DIM;  // embeddings is [BN, E]

    const int sigSmem = (E_DIM * H1 + SIG_ROWS * EPAD) * (int)sizeof(float); // ~65 KB
    static bool attrSet = false;
    if (!attrSet) {
        cudaFuncSetAttribute(sigma_kernel, cudaFuncAttributeMaxDynamicSharedMemorySize, sigSmem);
        attrSet = true;
    }

    const int sigmaBlocks = (BN + SIG_ROWS - 1) / SIG_ROWS;
    sigma_kernel<<<sigmaBlocks, SIG_THREADS, sigSmem>>>(emb, mu, w1, b1, w2, b2, w3, b3, BN);

    const int streamBlocks = (BN + ROWS_PER_BLK - 1) / ROWS_PER_BLK;
    rbf_stream_kernel<<<streamBlocks, 512>>>(z, out, M, BN);
}